// round 2
// baseline (speedup 1.0000x reference)
#include <cuda_runtime.h>
#include <math.h>

#define BB 2
#define NN 512
#define MM 512
#define CC 64
#define O1 128
#define O2 64
#define O3 32
#define ROWS (BB*NN)
#define CNT1 524288.0f
#define CNT3 1024.0f
#define EPS_BN 1e-5f

__device__ float g_srcn[BB*NN*CC];
__device__ float g_dstn[BB*MM*CC];
__device__ float g_A[BB*NN*O1];
__device__ float g_D[BB*MM*O1];
__device__ float g_idxy[BB*MM*2];
__device__ float g_cos[BB*NN*MM];
__device__ float g_rowinv[BB*NN];
__device__ float g_colinv[BB*MM];
__device__ float g_stat1[2*O1];
__device__ float g_bn1[2*O1];
__device__ float g_w1s[3*O1];
__device__ float g_h2[(size_t)ROWS*O2*MM];
__device__ float g_stat2[2*O2];
__device__ float g_bn2[2*O2];
__device__ float g_attv[ROWS*O2];
__device__ float g_tv[ROWS*O3];
__device__ float g_stat3[2*O3];
__device__ float g_bn3[2*O3];

__device__ __forceinline__ void fma2(unsigned long long &c, unsigned long long a, unsigned long long b) {
    asm("fma.rn.f32x2 %0, %1, %2, %0;" : "+l"(c) : "l"(a), "l"(b));
}
__device__ __forceinline__ unsigned long long dup2(float x) {
    unsigned long long r;
    asm("mov.b64 %0, {%1, %1};" : "=l"(r) : "r"(__float_as_uint(x)));
    return r;
}

__global__ void k_zero() {
    int t = threadIdx.x;
    if (t < 2*O1) g_stat1[t] = 0.f;
    if (t < 2*O2) g_stat2[t] = 0.f;
    if (t < 2*O3) g_stat3[t] = 0.f;
}

// per (b,m): dst_n, idx_xy, D[b,m,:]
__global__ void k_prep_dst(const float* __restrict__ RF3, const float* __restrict__ RF3i,
                           const float* __restrict__ W1) {
    int b = blockIdx.x / MM, m = blockIdx.x % MM;
    int t = threadIdx.x; // 128
    __shared__ float rf[CC], red[CC], sidx[3];
    if (t < CC) { float v = RF3[((size_t)(b*CC + t))*MM + m]; rf[t] = v; red[t] = v*v; }
    if (t >= CC && t < CC+3) sidx[t-CC] = RF3i[((size_t)(b*3 + (t-CC)))*MM + m];
    __syncthreads();
    if (t < 32) red[t] += red[t+32];
    __syncthreads();
    if (t == 0) {
        float s = 0.f;
        #pragma unroll
        for (int i = 0; i < 32; i++) s += red[i];
        red[0] = 1.0f / fmaxf(sqrtf(s), 1e-12f);
    }
    __syncthreads();
    float inv = red[0];
    if (t < CC) g_dstn[(b*MM+m)*CC + t] = rf[t]*inv;
    if (t < 2)  g_idxy[(b*MM+m)*2 + t] = sidx[t];
    float ix = sidx[0], iy = sidx[1];
    int o = t;
    float d = ix*(W1[5*O1+o] - W1[7*O1+o]) + iy*(W1[6*O1+o] - W1[8*O1+o]);
    #pragma unroll 8
    for (int c = 0; c < CC; c++) d += rf[c]*W1[(10+CC+c)*O1 + o];
    g_D[(b*MM+m)*O1 + o] = d;
}

// per (b,n): src_n, A[b,n,:] (includes b1)
__global__ void k_prep_src(const float* __restrict__ wxyz, const float* __restrict__ wpts,
                           const float* __restrict__ lz, const float* __restrict__ W1,
                           const float* __restrict__ b1) {
    int b = blockIdx.x / NN, n = blockIdx.x % NN;
    int t = threadIdx.x; // 128
    __shared__ float wp[CC], red[CC], sx[4];
    if (t < CC) { float v = wpts[(b*NN+n)*CC + t]; wp[t] = v; red[t] = v*v; }
    if (t >= CC && t < CC+3) sx[t-CC] = wxyz[(b*NN+n)*3 + (t-CC)];
    if (t == CC+3) sx[3] = lz[b*NN+n];
    __syncthreads();
    if (t < 32) red[t] += red[t+32];
    __syncthreads();
    if (t == 0) {
        float s = 0.f;
        #pragma unroll
        for (int i = 0; i < 32; i++) s += red[i];
        red[0] = 1.0f / fmaxf(sqrtf(s), 1e-12f);
    }
    __syncthreads();
    float inv = red[0];
    if (t < CC) g_srcn[(b*NN+n)*CC + t] = wp[t]*inv;
    float l = sx[3];
    int o = t;
    float a = sx[0]*l*W1[0*O1+o] + sx[1]*l*W1[1*O1+o] + sx[2]*l*W1[2*O1+o]
            + wp[0]*W1[3*O1+o] + wp[1]*W1[4*O1+o]
            + sx[0]*W1[7*O1+o] + sx[1]*W1[8*O1+o] + b1[o];
    #pragma unroll 8
    for (int c = 0; c < CC; c++) a += wp[c]*W1[(10+c)*O1 + o];
    g_A[(b*NN+n)*O1 + o] = a;
}

// per (b,n): cos[b,n,:] + row max
__global__ void k_cos() {
    int b = blockIdx.x / NN, n = blockIdx.x % NN;
    int t = threadIdx.x; // 128
    __shared__ float src[CC];
    __shared__ float dst[CC][132];
    __shared__ float red[128];
    if (t < CC) src[t] = g_srcn[(b*NN+n)*CC + t];
    float mx = -1e30f;
    for (int mt = 0; mt < MM; mt += 128) {
        __syncthreads();
        for (int idx = t; idx < 128*CC; idx += 128) {
            int mm = idx >> 6, c = idx & 63;
            dst[c][mm] = g_dstn[(b*MM + mt + mm)*CC + c];
        }
        __syncthreads();
        float acc = 0.f;
        #pragma unroll 8
        for (int c = 0; c < CC; c++) acc += src[c]*dst[c][t];
        g_cos[((size_t)(b*NN+n))*MM + mt + t] = acc;
        mx = fmaxf(mx, acc);
    }
    red[t] = mx;
    __syncthreads();
    for (int s = 64; s > 0; s >>= 1) { if (t < s) red[t] = fmaxf(red[t], red[t+s]); __syncthreads(); }
    if (t == 0) g_rowinv[b*NN+n] = 1.0f/(red[0] + 1e-6f);
}

__global__ void k_colmax() {
    int id = blockIdx.x*128 + threadIdx.x; // BB*MM ids
    int b = id >> 9, m = id & (MM-1);
    float mx = -1e30f;
    #pragma unroll 8
    for (int n = 0; n < NN; n++) mx = fmaxf(mx, g_cos[((size_t)(b*NN+n))*MM + m]);
    g_colinv[b*MM+m] = 1.0f/(mx + 1e-10f);
}

// BN1 stats over raw h1pre
__global__ void k_stats1(const float* __restrict__ W1, const float* __restrict__ wxyz) {
    int b = blockIdx.x / NN, n = blockIdx.x % NN;
    int t = threadIdx.x; // 128
    __shared__ float ess[3*MM];
    float wx = wxyz[(b*NN+n)*3+0], wy = wxyz[(b*NN+n)*3+1];
    float invr = g_rowinv[b*NN+n];
    for (int m = t; m < MM; m += 128) {
        float ix = g_idxy[(b*MM+m)*2+0], iy = g_idxy[(b*MM+m)*2+1];
        float ex = wx-ix, ey = wy-iy;
        ess[m] = sqrtf(ex*ex + ey*ey);
        float cv = g_cos[((size_t)(b*NN+n))*MM + m];
        ess[MM+m]   = cv*invr;
        ess[2*MM+m] = cv*g_colinv[b*MM+m];
    }
    __syncthreads();
    int o = t;
    float a = g_A[(b*NN+n)*O1 + o];
    float wn = W1[9*O1+o], w1s = W1[138*O1+o], w2s = W1[139*O1+o];
    float sum = 0.f, sq = 0.f;
    const float* Dp = &g_D[(size_t)(b*MM)*O1 + o];
    #pragma unroll 4
    for (int m = 0; m < MM; m++) {
        float h = a + Dp[(size_t)m*O1] + ess[m]*wn + ess[MM+m]*w1s + ess[2*MM+m]*w2s;
        sum += h; sq += h*h;
    }
    atomicAdd(&g_stat1[o], sum);
    atomicAdd(&g_stat1[O1+o], sq);
}

__global__ void k_fin1(const float* __restrict__ W1, const float* __restrict__ g1,
                       const float* __restrict__ be1) {
    int o = threadIdx.x; // 128
    float mean = g_stat1[o]/CNT1;
    float var  = g_stat1[O1+o]/CNT1 - mean*mean;
    float sc = g1[o]*rsqrtf(var + EPS_BN);
    float sh = be1[o] - mean*sc;
    g_bn1[o] = sc; g_bn1[O1+o] = sh;
    g_w1s[o]      = W1[9*O1+o]*sc;
    g_w1s[O1+o]   = W1[138*O1+o]*sc;
    g_w1s[2*O1+o] = W1[139*O1+o]*sc;
}

__global__ void k_rescale() {
    int idx = blockIdx.x*256 + threadIdx.x; // 2*ROWS*O1
    int o = idx & (O1-1);
    float sc = g_bn1[o];
    if (idx < ROWS*O1) g_A[idx] = fmaf(g_A[idx], sc, g_bn1[O1+o]);
    else               g_D[idx - ROWS*O1] *= sc;
}

// fused: reconstruct relu(bn1(h1)) tile -> GEMM2 (f32x2) -> store h2pre + BN2 stats
#define K4_SMEMF (O1*O2 + O1*129 + 3*MM)
__global__ void __launch_bounds__(256, 2)
k_gemm2(const float* __restrict__ W2, const float* __restrict__ b2p,
        const float* __restrict__ wxyz) {
    extern __shared__ float sm[];
    float* s_w2  = sm;               // 128*64
    float* s_r   = sm + O1*O2;       // 128*129
    float* s_ess = s_r + O1*129;     // 3*512
    int b = blockIdx.x / NN, n = blockIdx.x % NN;
    int bn = b*NN + n;
    int t = threadIdx.x;

    for (int i = t; i < O1*O2; i += 256) s_w2[i] = W2[i];
    float wx = wxyz[bn*3+0], wy = wxyz[bn*3+1];
    float invr = g_rowinv[bn];
    for (int m = t; m < MM; m += 256) {
        float ix = g_idxy[(b*MM+m)*2+0], iy = g_idxy[(b*MM+m)*2+1];
        float ex = wx-ix, ey = wy-iy;
        s_ess[m] = sqrtf(ex*ex + ey*ey);
        float cv = g_cos[((size_t)bn)*MM + m];
        s_ess[MM+m]   = cv*invr;
        s_ess[2*MM+m] = cv*g_colinv[b*MM+m];
    }
    int o = t & (O1-1), half = t >> 7;
    float a   = g_A[bn*O1 + o];
    float wn  = g_w1s[o], w1s = g_w1s[O1+o], w2sv = g_w1s[2*O1+o];
    int jg = t >> 5, mg = t & 31;
    float bj[8];
    #pragma unroll
    for (int jj = 0; jj < 8; jj++) bj[jj] = b2p[jg*8 + jj];
    float sum2[8], sq2[8];
    #pragma unroll
    for (int jj = 0; jj < 8; jj++) { sum2[jj] = 0.f; sq2[jj] = 0.f; }
    __syncthreads();

    for (int mt = 0; mt < MM; mt += 128) {
        const float* Dp = &g_D[(size_t)(b*MM + mt + half*64)*O1 + o];
        #pragma unroll 4
        for (int i = 0; i < 64; i++) {
            int ml = half*64 + i, m = mt + ml;
            float h = a + Dp[(size_t)i*O1] + s_ess[m]*wn + s_ess[MM+m]*w1s + s_ess[2*MM+m]*w2sv;
            s_r[o*129 + ml] = fmaxf(h, 0.0f);
        }
        __syncthreads();

        unsigned long long c2[4][4];
        #pragma unroll
        for (int i = 0; i < 4; i++)
            #pragma unroll
            for (int jp = 0; jp < 4; jp++) c2[i][jp] = 0ull;
        #pragma unroll 2
        for (int k = 0; k < O1; k++) {
            const float* rrow = &s_r[k*129];
            const unsigned long long* wrow = (const unsigned long long*)&s_w2[k*O2 + jg*8];
            unsigned long long w0 = wrow[0], w1 = wrow[1], w2 = wrow[2], w3 = wrow[3];
            #pragma unroll
            for (int i = 0; i < 4; i++) {
                unsigned long long rd = dup2(rrow[mg + 32*i]);
                fma2(c2[i][0], rd, w0);
                fma2(c2[i][1], rd, w1);
                fma2(c2[i][2], rd, w2);
                fma2(c2[i][3], rd, w3);
            }
        }
        #pragma unroll
        for (int i = 0; i < 4; i++) {
            int m = mt + mg + 32*i;
            #pragma unroll
            for (int jp = 0; jp < 4; jp++) {
                float lo = __uint_as_float((unsigned)(c2[i][jp] & 0xffffffffull)) + bj[2*jp];
                float hi = __uint_as_float((unsigned)(c2[i][jp] >> 32)) + bj[2*jp+1];
                int j0 = jg*8 + 2*jp;
                g_h2[((size_t)bn*O2 + j0  )*MM + m] = lo;
                g_h2[((size_t)bn*O2 + j0+1)*MM + m] = hi;
                sum2[2*jp]   += lo; sq2[2*jp]   += lo*lo;
                sum2[2*jp+1] += hi; sq2[2*jp+1] += hi*hi;
            }
        }
        __syncthreads();
    }
    #pragma unroll
    for (int jj = 0; jj < 8; jj++) {
        float s = sum2[jj], q = sq2[jj];
        #pragma unroll
        for (int off = 16; off > 0; off >>= 1) {
            s += __shfl_down_sync(0xffffffffu, s, off);
            q += __shfl_down_sync(0xffffffffu, q, off);
        }
        if (mg == 0) {
            atomicAdd(&g_stat2[jg*8+jj], s);
            atomicAdd(&g_stat2[O2 + jg*8+jj], q);
        }
    }
}

__global__ void k_fin2(const float* __restrict__ g2, const float* __restrict__ be2) {
    int j = threadIdx.x; // 64
    float mean = g_stat2[j]/CNT1;
    float var  = g_stat2[O2+j]/CNT1 - mean*mean;
    float sc = g2[j]*rsqrtf(var + EPS_BN);
    g_bn2[j] = sc; g_bn2[O2+j] = be2[j] - mean*sc;
}

// per (b,n): channel-max -> softmax over m -> weighted sum -> att[bn,64]
__global__ void k_att() {
    int bn = blockIdx.x;
    int t = threadIdx.x; // 512
    __shared__ float sc2[O2], sh2[O2], aw[MM], red[512];
    if (t < O2) { sc2[t] = g_bn2[t]; sh2[t] = g_bn2[O2+t]; }
    __syncthreads();
    float mx = -1e30f;
    #pragma unroll 8
    for (int j = 0; j < O2; j++) {
        float v = g_h2[((size_t)bn*O2 + j)*MM + t];
        float y = fmaxf(fmaf(sc2[j], v, sh2[j]), 0.0f);
        mx = fmaxf(mx, y);
    }
    red[t] = mx;
    __syncthreads();
    for (int s = 256; s > 0; s >>= 1) { if (t < s) red[t] = fmaxf(red[t], red[t+s]); __syncthreads(); }
    float mall = red[0];
    __syncthreads();
    float e = expf(mx - mall);
    red[t] = e;
    __syncthreads();
    for (int s = 256; s > 0; s >>= 1) { if (t < s) red[t] += red[t+s]; __syncthreads(); }
    float inv = 1.0f/red[0];
    aw[t] = e*inv;
    __syncthreads();

    int w = t >> 5, lane = t & 31;
    int j0 = w*4;
    float scl[4], shl[4], acc[4];
    #pragma unroll
    for (int q = 0; q < 4; q++) { scl[q]=sc2[j0+q]; shl[q]=sh2[j0+q]; acc[q]=0.f; }
    for (int mt = 0; mt < MM; mt += 32) {
        int m = mt + lane;
        float awm = aw[m];
        #pragma unroll
        for (int q = 0; q < 4; q++) {
            float v = g_h2[((size_t)bn*O2 + j0+q)*MM + m];
            float y = fmaxf(fmaf(scl[q], v, shl[q]), 0.0f);
            acc[q] += awm*y;
        }
    }
    #pragma unroll
    for (int q = 0; q < 4; q++) {
        float s = acc[q];
        #pragma unroll
        for (int off = 16; off > 0; off >>= 1) s += __shfl_down_sync(0xffffffffu, s, off);
        if (lane == 0) g_attv[bn*O2 + j0+q] = s;
    }
}

__global__ void k_head(const float* __restrict__ M1w, const float* __restrict__ M1b) {
    int bn = blockIdx.x;
    int j = threadIdx.x; // 32
    float s = M1b[j];
    #pragma unroll 8
    for (int c = 0; c < O2; c++) s += g_attv[bn*O2+c]*M1w[c*O3+j];
    g_tv[bn*O3+j] = s;
    atomicAdd(&g_stat3[j], s);
    atomicAdd(&g_stat3[O3+j], s*s);
}

__global__ void k_fin3(const float* __restrict__ M1g, const float* __restrict__ M1be) {
    int j = threadIdx.x; // 32
    float mean = g_stat3[j]/CNT3;
    float var  = g_stat3[O3+j]/CNT3 - mean*mean;
    float sc = M1g[j]*rsqrtf(var + EPS_BN);
    g_bn3[j] = sc; g_bn3[O3+j] = M1be[j] - mean*sc;
}

__global__ void k_final(const float* __restrict__ M2w, const float* __restrict__ M2b,
                        float* __restrict__ out) {
    int bn = blockIdx.x*128 + threadIdx.x; // 1024
    float l0 = M2b[0], l1 = M2b[1];
    #pragma unroll 8
    for (int c = 0; c < O3; c++) {
        float y = fmaxf(fmaf(g_bn3[c], g_tv[bn*O3+c], g_bn3[O3+c]), 0.0f);
        l0 += y*M2w[c*2+0];
        l1 += y*M2w[c*2+1];
    }
    out[bn*2+0] = l0;
    out[bn*2+1] = l1;
}

extern "C" void kernel_launch(void* const* d_in, const int* in_sizes, int n_in,
                              void* d_out, int out_size) {
    const float* wxyz = (const float*)d_in[0];
    const float* wpts = (const float*)d_in[1];
    const float* RF3  = (const float*)d_in[2];
    const float* RF3i = (const float*)d_in[3];
    const float* lz   = (const float*)d_in[4];
    const float* W1   = (const float*)d_in[5];
    const float* b1   = (const float*)d_in[6];
    const float* g1   = (const float*)d_in[7];
    const float* be1  = (const float*)d_in[8];
    const float* W2   = (const float*)d_in[9];
    const float* b2   = (const float*)d_in[10];
    const float* g2   = (const float*)d_in[11];
    const float* be2  = (const float*)d_in[12];
    const float* M1w  = (const float*)d_in[13];
    const float* M1b  = (const float*)d_in[14];
    const float* M1g  = (const float*)d_in[15];
    const float* M1be = (const float*)d_in[16];
    const float* M2w  = (const float*)d_in[17];
    const float* M2b  = (const float*)d_in[18];
    float* out = (float*)d_out;

    cudaFuncSetAttribute(k_gemm2, cudaFuncAttributeMaxDynamicSharedMemorySize, K4_SMEMF*4);

    k_zero<<<1, 256>>>();
    k_prep_dst<<<BB*MM, 128>>>(RF3, RF3i, W1);
    k_prep_src<<<BB*NN, 128>>>(wxyz, wpts, lz, W1, b1);
    k_cos<<<BB*NN, 128>>>();
    k_colmax<<<(BB*MM)/128, 128>>>();
    k_stats1<<<BB*NN, 128>>>(W1, wxyz);
    k_fin1<<<1, 128>>>(W1, g1, be1);
    k_rescale<<<(2*ROWS*O1)/256, 256>>>();
    k_gemm2<<<BB*NN, 256, K4_SMEMF*4>>>(W2, b2, wxyz);
    k_fin2<<<1, 64>>>(g2, be2);
    k_att<<<BB*NN, 512>>>();
    k_head<<<ROWS, 32>>>(M1w, M1b);
    k_fin3<<<1, 32>>>(M1g, M1be);
    k_final<<<ROWS/128, 128>>>(M2w, M2b, out);
}